// round 8
// baseline (speedup 1.0000x reference)
#include <cuda_runtime.h>
#include <cuda_bf16.h>
#include <cstdint>

// Problem constants
#define BATCH 32
#define N_ROI 2000
#define N_GT  100
#define N_LAB 21
#define K_POS 64
#define ROWS_PER_B (N_ROI * N_LAB)            // 42000
#define DELTA_FLOATS (BATCH * ROWS_PER_B * 4) // 5,376,000
#define TOTAL_ROWS (BATCH * ROWS_PER_B)       // 1,344,000  (also = label floats)
#define LAB_VEC4 (TOTAL_ROWS / 4)             // 336,000 float4s of labels
#define RPB 64                                 // rois per block in iou kernel

// Scratch (device globals; no runtime allocation)
__device__ unsigned int g_merged[BATCH * N_ROI];
__device__ int          g_maxidx[BATCH * N_ROI];
__device__ int          g_label [BATCH * N_ROI];   // gt label if positive, else -1
__device__ float4       g_delta [BATCH * N_ROI];   // valid only when positive

// ---------------------------------------------------------------------------
// Kernel A: per-roi max IoU + first-argmax over 100 gt boxes.
// Algebra: IoU = inter/(S - inter), S = bb_area + gt_area, strictly increasing
// in inter/S -> argmax over gt needs no union subtraction in the loop.
// 4 threads per roi (25 gt each) + shuffle reduction; comparison is
// cross-multiplied (S > 0). Zero-overlap ties exact: 0 > 0 false.
// Out-of-range rois are clamped (duplicate compute, guarded store).
// ---------------------------------------------------------------------------
__global__ void __launch_bounds__(256) iou_kernel(const float4* __restrict__ roi,
                                                  const float4* __restrict__ gt)
{
    __shared__ float4 sg[N_GT];
    __shared__ float  sga[N_GT];
    const int b = blockIdx.y;
    const int t = threadIdx.x;

    if (t < N_GT) {
        const float4 g = gt[b * N_GT + t];
        sg[t]  = g;
        sga[t] = __fmul_rn(__fsub_rn(g.z, g.x), __fsub_rn(g.w, g.y));
    }
    __syncthreads();

    const int local = t >> 2;                 // 0..63 : roi within block
    const int seg   = t & 3;                  // 0..3  : gt segment
    const int n     = blockIdx.x * RPB + local;
    const int nc    = (n < N_ROI) ? n : (N_ROI - 1);   // clamp: no guard in loop

    const float4 q = roi[b * N_ROI + nc];
    const float by1 = q.x, bx1 = q.y, by2 = q.z, bx2 = q.w;
    const float bb_area = __fmul_rn(__fsub_rn(by2, by1), __fsub_rn(bx2, bx1));

    const int m0 = seg * 25;
    float aI = 0.0f, aS = 1.0f; int ai = m0;  // best inter / its S / index

#pragma unroll
    for (int i = 0; i < 25; ++i) {
        const int m = m0 + i;
        const float4 g = sg[m];
        const float xt = fmaxf(bx1, g.y);
        const float yt = fmaxf(by1, g.x);
        const float xb = fminf(bx2, g.w);
        const float yb = fminf(by2, g.z);
        const float iw = fmaxf(__fsub_rn(xb, xt), 0.0f);
        const float ih = __fsub_rn(yb, yt);            // may be negative
        const float inter = __fmul_rn(iw, ih);          // <=0 when no overlap
        const float S = __fadd_rn(bb_area, sga[m]);     // > 0
        // inter/S > aI/aS  <=>  inter*aS > aI*S   (S, aS > 0)
        if (__fmul_rn(inter, aS) > __fmul_rn(aI, S)) { aI = inter; aS = S; ai = m; }
    }

    // Reduce across the 4 lanes of this roi (lanes are consecutive in warp).
#pragma unroll
    for (int off = 1; off < 4; off <<= 1) {
        const float oI = __shfl_xor_sync(0xFFFFFFFFu, aI, off);
        const float oS = __shfl_xor_sync(0xFFFFFFFFu, aS, off);
        const int   oi = __shfl_xor_sync(0xFFFFFFFFu, ai, off);
        const float x = __fmul_rn(oI, aS);
        const float y = __fmul_rn(aI, oS);
        if (x > y || (x == y && oi < ai)) { aI = oI; aS = oS; ai = oi; }
    }

    if (seg == 0 && n < N_ROI) {
        const float best = (aI > 0.0f) ? __fdividef(aI, __fsub_rn(aS, aI)) : 0.0f;
        g_merged[b * N_ROI + n] = __float_as_uint(best);  // >=0 -> monotone bits
        g_maxidx[b * N_ROI + n] = ai;
    }
}

// ---------------------------------------------------------------------------
// Kernel B: per-batch top-64 selection (exact stable-sort semantics) and
// per-roi label/delta records. One block per batch, 1024 threads, 2 rois/thr.
// ---------------------------------------------------------------------------
__global__ void __launch_bounds__(1024) select_kernel(const float4* __restrict__ roi,
                                                      const float4* __restrict__ gt,
                                                      const int*    __restrict__ gtlab)
{
    __shared__ unsigned int hist[256];
    __shared__ unsigned int ssum[256];
    __shared__ unsigned int s_prefix, s_k;
    __shared__ int warp_sums[32];

    const int b = blockIdx.x;
    const int t = threadIdx.x;
    const int n0 = 2 * t, n1 = 2 * t + 1;
    const bool act = (n0 < N_ROI);
    const int lane = t & 31, wid = t >> 5;

    const unsigned int* gm = g_merged + b * N_ROI;
    unsigned v0 = 0u, v1 = 0u;
    if (act) { v0 = gm[n0]; v1 = gm[n1]; }
    if (t == 0) { s_prefix = 0u; s_k = K_POS; }
    __syncthreads();

    // 4-pass MSB radix select of the K_POS-th largest value (1-indexed).
#pragma unroll
    for (int pass = 0; pass < 4; ++pass) {
        const int shift = 24 - 8 * pass;
        if (t < 256) hist[t] = 0u;
        __syncthreads();
        const unsigned pfx = s_prefix;
        const unsigned kk0 = s_k;
        const unsigned hm = (pass == 0) ? 0u
                          : (0xFFFFFFFFu << ((shift + 8 > 31) ? 31 : shift + 8));
        // match-aggregated histogram (bin 0 is extremely hot: all zero-IoU rois)
#pragma unroll
        for (int s = 0; s < 2; ++s) {
            const unsigned v = (s == 0) ? v0 : v1;
            unsigned key = 0x100u;  // no-op key
            unsigned bin = 0u;
            if (act && (v & hm) == (pfx & hm)) { bin = (v >> shift) & 255u; key = bin; }
            const unsigned mmask = __match_any_sync(0xFFFFFFFFu, key);
            if (key != 0x100u) {
                const int leader = __ffs(mmask) - 1;
                if (lane == leader) atomicAdd(&hist[bin], (unsigned)__popc(mmask));
            }
        }
        __syncthreads();
        // single-warp suffix (descending cumulative) sum over 256 bins
        if (t < 32) {
            unsigned v[8];
            unsigned sum = 0u;
#pragma unroll
            for (int i = 0; i < 8; ++i) { v[i] = hist[t * 8 + i]; sum += v[i]; }
            unsigned suf = sum;
#pragma unroll
            for (int off = 1; off < 32; off <<= 1) {
                const unsigned x = __shfl_down_sync(0xFFFFFFFFu, suf, off);
                if (t + off < 32) suf += x;
            }
            unsigned acc = suf - sum;  // sum of lanes > t
#pragma unroll
            for (int i = 7; i >= 0; --i) { acc += v[i]; ssum[t * 8 + i] = acc; }
        }
        __syncthreads();
        if (t < 256) {
            const unsigned cum   = ssum[t];
            const unsigned above = (t < 255) ? ssum[t + 1] : 0u;
            if (cum >= kk0 && above < kk0) {   // unique winner bin
                s_prefix = pfx | ((unsigned)t << shift);
                s_k = kk0 - above;             // rank among ties at this value
            }
        }
        __syncthreads();
    }

    const unsigned T  = s_prefix;   // bits of the 64th-largest merged IoU
    const unsigned kk = s_k;        // number of tie slots (index-ascending)

    // Exclusive prefix count of ties (preserves original-index stable order)
    const int f0 = (act && v0 == T) ? 1 : 0;
    const int f1 = (act && v1 == T) ? 1 : 0;
    const int c  = f0 + f1;
    int inc = c;
#pragma unroll
    for (int off = 1; off < 32; off <<= 1) {
        const int x = __shfl_up_sync(0xFFFFFFFFu, inc, off);
        if (lane >= off) inc += x;
    }
    if (lane == 31) warp_sums[wid] = inc;
    __syncthreads();
    if (t < 32) {
        const int v = warp_sums[t];
        int iv = v;
#pragma unroll
        for (int off = 1; off < 32; off <<= 1) {
            const int x = __shfl_up_sync(0xFFFFFFFFu, iv, off);
            if (t >= off) iv += x;
        }
        warp_sums[t] = iv - v;  // exclusive
    }
    __syncthreads();
    const int excl = warp_sums[wid] + (inc - c);

    if (!act) return;

    const bool pos0 = (v0 > T) || (f0 && (unsigned)excl        < kk);
    const bool pos1 = (v1 > T) || (f1 && (unsigned)(excl + f0) < kk);

#pragma unroll
    for (int s = 0; s < 2; ++s) {
        const int n = (s == 0) ? n0 : n1;
        const bool pos = (s == 0) ? pos0 : pos1;
        const int gi = b * N_ROI + n;
        if (!pos) { g_label[gi] = -1; continue; }
        const int mi = g_maxidx[gi];
        const float4 q = roi[gi];
        const float4 g = gt[b * N_GT + mi];
        float bw = q.w - q.y;
        float bh = q.z - q.x;
        const float bcx = q.y + 0.5f * bw;
        const float bcy = q.x + 0.5f * bh;
        const float gw = g.w - g.y;
        const float gh = g.z - g.x;
        const float gcx = g.y + 0.5f * gw;
        const float gcy = g.x + 0.5f * gh;
        bw = (bw == 0.0f) ? 1e-3f : bw;
        bh = (bh == 0.0f) ? 1e-3f : bh;
        const float dx = (gw == 0.0f) ? 0.0f : (gcx - bcx) / bw;
        const float dy = (gh == 0.0f) ? 0.0f : (gcy - bcy) / bh;
        const float dw = (gw == 0.0f) ? 0.0f : logf(gw / bw);
        const float dh = (gh == 0.0f) ? 0.0f : logf(gh / bh);
        g_delta[gi] = make_float4(dy, dx, dh, dw);
        g_label[gi] = gtlab[b * N_GT + mi];
    }
}

// ---------------------------------------------------------------------------
// Kernel C1: delta rows. One thread per (b, n, l): one STG.128.
// ---------------------------------------------------------------------------
__global__ void __launch_bounds__(256) write_delta_kernel(float4* __restrict__ out)
{
    const int r = blockIdx.x * 256 + threadIdx.x;
    if (r >= ROWS_PER_B) return;
    const int b = blockIdx.y;
    const int n = r / N_LAB;
    const int l = r - n * N_LAB;

    const int lab = g_label[b * N_ROI + n];
    float4 dv = make_float4(0.f, 0.f, 0.f, 0.f);
    if (lab == l) dv = g_delta[b * N_ROI + n];
    out[b * ROWS_PER_B + r] = dv;
}

// ---------------------------------------------------------------------------
// Kernel C2: one-hot labels as pure float4 stores. Thread i covers label
// array elements [4i, 4i+4); spans at most two rois (cached loads).
// ---------------------------------------------------------------------------
__global__ void __launch_bounds__(256) write_label_kernel(float4* __restrict__ outLab)
{
    const int i = blockIdx.x * 256 + threadIdx.x;
    if (i >= LAB_VEC4) return;
    const int p  = i * 4;                 // flat label index
    const int rr = p / N_LAB;             // flat roi index (b*N_ROI + n)
    const int l0 = p - rr * N_LAB;        // label slot of element 0

    const int labA = g_label[rr];
    const int eA = (labA < 0) ? 0 : labA;
    int eB = eA;
    if (l0 + 3 >= N_LAB) {                // crosses into next roi
        const int labB = g_label[rr + 1];
        eB = (labB < 0) ? 0 : labB;
    }

    float v[4];
#pragma unroll
    for (int j = 0; j < 4; ++j) {
        const int l = l0 + j;
        const bool second = (l >= N_LAB);
        const int ll = second ? (l - N_LAB) : l;
        const int ee = second ? eB : eA;
        v[j] = (ll == ee) ? 1.0f : 0.0f;
    }
    outLab[i] = make_float4(v[0], v[1], v[2], v[3]);
}

// ---------------------------------------------------------------------------
extern "C" void kernel_launch(void* const* d_in, const int* in_sizes, int n_in,
                              void* d_out, int out_size)
{
    const float4* roi   = (const float4*)d_in[0];
    const float4* gt    = (const float4*)d_in[1];
    const int*    gtlab = (const int*)d_in[2];
    float*        out   = (float*)d_out;

    dim3 gA((N_ROI + RPB - 1) / RPB, BATCH);
    iou_kernel<<<gA, 256>>>(roi, gt);
    select_kernel<<<BATCH, 1024>>>(roi, gt, gtlab);
    dim3 gC((ROWS_PER_B + 255) / 256, BATCH);
    write_delta_kernel<<<gC, 256>>>((float4*)out);
    write_label_kernel<<<(LAB_VEC4 + 255) / 256, 256>>>(
        (float4*)(out + DELTA_FLOATS));
}

// round 9
// speedup vs baseline: 1.0125x; 1.0125x over previous
#include <cuda_runtime.h>
#include <cuda_bf16.h>
#include <cstdint>

// Problem constants
#define BATCH 32
#define N_ROI 2000
#define N_GT  100
#define N_LAB 21
#define K_POS 64
#define ROWS_PER_B (N_ROI * N_LAB)            // 42000
#define DELTA_FLOATS (BATCH * ROWS_PER_B * 4) // 5,376,000
#define TOTAL_ROWS (BATCH * ROWS_PER_B)       // 1,344,000 (delta float4s; also label floats)
#define LAB_VEC4 (TOTAL_ROWS / 4)             // 336,000 label float4s
#define ALL_VEC4 (TOTAL_ROWS + LAB_VEC4)      // 1,680,000 fused float4 stores
#define RPB 64                                 // rois per block in iou kernel

// Scratch (device globals; no runtime allocation)
__device__ unsigned int g_merged[BATCH * N_ROI];
__device__ int          g_maxidx[BATCH * N_ROI];
__device__ int          g_label [BATCH * N_ROI];   // gt label if positive, else -1
__device__ float4       g_delta [BATCH * N_ROI];   // valid only when positive

// ---------------------------------------------------------------------------
// Kernel A: per-roi max IoU + first-argmax over 100 gt boxes.
// Algebra: IoU = inter/(S - inter), S = bb_area + gt_area, strictly increasing
// in inter/S -> argmax over gt needs no union subtraction in the loop.
// 4 threads per roi (25 gt each) + shuffle reduction; comparison is
// cross-multiplied (S > 0). Zero-overlap ties exact: 0 > 0 false.
// ---------------------------------------------------------------------------
__global__ void __launch_bounds__(256) iou_kernel(const float4* __restrict__ roi,
                                                  const float4* __restrict__ gt)
{
    __shared__ float4 sg[N_GT];
    __shared__ float  sga[N_GT];
    const int b = blockIdx.y;
    const int t = threadIdx.x;

    if (t < N_GT) {
        const float4 g = gt[b * N_GT + t];
        sg[t]  = g;
        sga[t] = __fmul_rn(__fsub_rn(g.z, g.x), __fsub_rn(g.w, g.y));
    }
    __syncthreads();

    const int local = t >> 2;                 // 0..63 : roi within block
    const int seg   = t & 3;                  // 0..3  : gt segment
    const int n     = blockIdx.x * RPB + local;
    const int nc    = (n < N_ROI) ? n : (N_ROI - 1);   // clamp: no guard in loop

    const float4 q = roi[b * N_ROI + nc];
    const float by1 = q.x, bx1 = q.y, by2 = q.z, bx2 = q.w;
    const float bb_area = __fmul_rn(__fsub_rn(by2, by1), __fsub_rn(bx2, bx1));

    const int m0 = seg * 25;
    float aI = 0.0f, aS = 1.0f; int ai = m0;  // best inter / its S / index

#pragma unroll
    for (int i = 0; i < 25; ++i) {
        const int m = m0 + i;
        const float4 g = sg[m];
        const float xt = fmaxf(bx1, g.y);
        const float yt = fmaxf(by1, g.x);
        const float xb = fminf(bx2, g.w);
        const float yb = fminf(by2, g.z);
        const float iw = fmaxf(__fsub_rn(xb, xt), 0.0f);
        const float ih = __fsub_rn(yb, yt);            // may be negative
        const float inter = __fmul_rn(iw, ih);          // <=0 when no overlap
        const float S = __fadd_rn(bb_area, sga[m]);     // > 0
        // inter/S > aI/aS  <=>  inter*aS > aI*S   (S, aS > 0)
        if (__fmul_rn(inter, aS) > __fmul_rn(aI, S)) { aI = inter; aS = S; ai = m; }
    }

    // Reduce across the 4 lanes of this roi (lanes are consecutive in warp).
#pragma unroll
    for (int off = 1; off < 4; off <<= 1) {
        const float oI = __shfl_xor_sync(0xFFFFFFFFu, aI, off);
        const float oS = __shfl_xor_sync(0xFFFFFFFFu, aS, off);
        const int   oi = __shfl_xor_sync(0xFFFFFFFFu, ai, off);
        const float x = __fmul_rn(oI, aS);
        const float y = __fmul_rn(aI, oS);
        if (x > y || (x == y && oi < ai)) { aI = oI; aS = oS; ai = oi; }
    }

    if (seg == 0 && n < N_ROI) {
        const float best = (aI > 0.0f) ? __fdividef(aI, __fsub_rn(aS, aI)) : 0.0f;
        g_merged[b * N_ROI + n] = __float_as_uint(best);  // >=0 -> monotone bits
        g_maxidx[b * N_ROI + n] = ai;
    }
}

// ---------------------------------------------------------------------------
// Kernel B: per-batch top-64 selection (exact stable-sort semantics) and
// per-roi label/delta records. One block per batch, 1024 threads, 2 rois/thr.
// ---------------------------------------------------------------------------
__global__ void __launch_bounds__(1024) select_kernel(const float4* __restrict__ roi,
                                                      const float4* __restrict__ gt,
                                                      const int*    __restrict__ gtlab)
{
    __shared__ unsigned int hist[256];
    __shared__ unsigned int ssum[256];
    __shared__ unsigned int s_prefix, s_k;
    __shared__ int warp_sums[32];

    const int b = blockIdx.x;
    const int t = threadIdx.x;
    const int n0 = 2 * t, n1 = 2 * t + 1;
    const bool act = (n0 < N_ROI);
    const int lane = t & 31, wid = t >> 5;

    const unsigned int* gm = g_merged + b * N_ROI;
    unsigned v0 = 0u, v1 = 0u;
    if (act) { v0 = gm[n0]; v1 = gm[n1]; }
    if (t == 0) { s_prefix = 0u; s_k = K_POS; }
    __syncthreads();

    // 4-pass MSB radix select of the K_POS-th largest value (1-indexed).
#pragma unroll
    for (int pass = 0; pass < 4; ++pass) {
        const int shift = 24 - 8 * pass;
        if (t < 256) hist[t] = 0u;
        __syncthreads();
        const unsigned pfx = s_prefix;
        const unsigned kk0 = s_k;
        const unsigned hm = (pass == 0) ? 0u
                          : (0xFFFFFFFFu << ((shift + 8 > 31) ? 31 : shift + 8));
        // match-aggregated histogram (bin 0 is extremely hot: all zero-IoU rois)
#pragma unroll
        for (int s = 0; s < 2; ++s) {
            const unsigned v = (s == 0) ? v0 : v1;
            unsigned key = 0x100u;  // no-op key
            unsigned bin = 0u;
            if (act && (v & hm) == (pfx & hm)) { bin = (v >> shift) & 255u; key = bin; }
            const unsigned mmask = __match_any_sync(0xFFFFFFFFu, key);
            if (key != 0x100u) {
                const int leader = __ffs(mmask) - 1;
                if (lane == leader) atomicAdd(&hist[bin], (unsigned)__popc(mmask));
            }
        }
        __syncthreads();
        // single-warp suffix (descending cumulative) sum over 256 bins
        if (t < 32) {
            unsigned v[8];
            unsigned sum = 0u;
#pragma unroll
            for (int i = 0; i < 8; ++i) { v[i] = hist[t * 8 + i]; sum += v[i]; }
            unsigned suf = sum;
#pragma unroll
            for (int off = 1; off < 32; off <<= 1) {
                const unsigned x = __shfl_down_sync(0xFFFFFFFFu, suf, off);
                if (t + off < 32) suf += x;
            }
            unsigned acc = suf - sum;  // sum of lanes > t
#pragma unroll
            for (int i = 7; i >= 0; --i) { acc += v[i]; ssum[t * 8 + i] = acc; }
        }
        __syncthreads();
        if (t < 256) {
            const unsigned cum   = ssum[t];
            const unsigned above = (t < 255) ? ssum[t + 1] : 0u;
            if (cum >= kk0 && above < kk0) {   // unique winner bin
                s_prefix = pfx | ((unsigned)t << shift);
                s_k = kk0 - above;             // rank among ties at this value
            }
        }
        __syncthreads();
    }

    const unsigned T  = s_prefix;   // bits of the 64th-largest merged IoU
    const unsigned kk = s_k;        // number of tie slots (index-ascending)

    // Exclusive prefix count of ties (preserves original-index stable order)
    const int f0 = (act && v0 == T) ? 1 : 0;
    const int f1 = (act && v1 == T) ? 1 : 0;
    const int c  = f0 + f1;
    int inc = c;
#pragma unroll
    for (int off = 1; off < 32; off <<= 1) {
        const int x = __shfl_up_sync(0xFFFFFFFFu, inc, off);
        if (lane >= off) inc += x;
    }
    if (lane == 31) warp_sums[wid] = inc;
    __syncthreads();
    if (t < 32) {
        const int v = warp_sums[t];
        int iv = v;
#pragma unroll
        for (int off = 1; off < 32; off <<= 1) {
            const int x = __shfl_up_sync(0xFFFFFFFFu, iv, off);
            if (t >= off) iv += x;
        }
        warp_sums[t] = iv - v;  // exclusive
    }
    __syncthreads();
    const int excl = warp_sums[wid] + (inc - c);

    if (!act) return;

    const bool pos0 = (v0 > T) || (f0 && (unsigned)excl        < kk);
    const bool pos1 = (v1 > T) || (f1 && (unsigned)(excl + f0) < kk);

#pragma unroll
    for (int s = 0; s < 2; ++s) {
        const int n = (s == 0) ? n0 : n1;
        const bool pos = (s == 0) ? pos0 : pos1;
        const int gi = b * N_ROI + n;
        if (!pos) { g_label[gi] = -1; continue; }
        const int mi = g_maxidx[gi];
        const float4 q = roi[gi];
        const float4 g = gt[b * N_GT + mi];
        float bw = q.w - q.y;
        float bh = q.z - q.x;
        const float bcx = q.y + 0.5f * bw;
        const float bcy = q.x + 0.5f * bh;
        const float gw = g.w - g.y;
        const float gh = g.z - g.x;
        const float gcx = g.y + 0.5f * gw;
        const float gcy = g.x + 0.5f * gh;
        bw = (bw == 0.0f) ? 1e-3f : bw;
        bh = (bh == 0.0f) ? 1e-3f : bh;
        const float dx = (gw == 0.0f) ? 0.0f : (gcx - bcx) / bw;
        const float dy = (gh == 0.0f) ? 0.0f : (gcy - bcy) / bh;
        const float dw = (gw == 0.0f) ? 0.0f : logf(gw / bw);
        const float dh = (gh == 0.0f) ? 0.0f : logf(gh / bh);
        g_delta[gi] = make_float4(dy, dx, dh, dw);
        g_label[gi] = gtlab[b * N_GT + mi];
    }
}

// ---------------------------------------------------------------------------
// Kernel C: fused output writer. One thread per output float4 (1.68M total):
//  i <  TOTAL_ROWS : delta row (flat_row/21 = flat roi index directly)
//  i >= TOTAL_ROWS : label float4 (spans at most two rois)
// ---------------------------------------------------------------------------
__global__ void __launch_bounds__(256) write_kernel(float4* __restrict__ out)
{
    const int i = blockIdx.x * 256 + threadIdx.x;
    if (i >= ALL_VEC4) return;

    if (i < TOTAL_ROWS) {
        // Delta row: flat row index i = flatroi*21 + l
        const int fr = i / N_LAB;             // flat roi index (b*N_ROI + n)
        const int l  = i - fr * N_LAB;
        const int lab = g_label[fr];
        float4 dv = make_float4(0.f, 0.f, 0.f, 0.f);
        if (lab == l) dv = g_delta[fr];
        out[i] = dv;
    } else {
        const int j  = i - TOTAL_ROWS;        // label float4 index
        const int p  = j * 4;                 // flat label element index
        const int rr = p / N_LAB;             // flat roi index
        const int l0 = p - rr * N_LAB;

        const int labA = g_label[rr];
        const int eA = (labA < 0) ? 0 : labA;
        int eB = eA;
        if (l0 + 3 >= N_LAB) {                // crosses into next roi
            const int labB = g_label[rr + 1];
            eB = (labB < 0) ? 0 : labB;
        }

        float v[4];
#pragma unroll
        for (int k = 0; k < 4; ++k) {
            const int l = l0 + k;
            const bool second = (l >= N_LAB);
            const int ll = second ? (l - N_LAB) : l;
            const int ee = second ? eB : eA;
            v[k] = (ll == ee) ? 1.0f : 0.0f;
        }
        out[i] = make_float4(v[0], v[1], v[2], v[3]);
    }
}

// ---------------------------------------------------------------------------
extern "C" void kernel_launch(void* const* d_in, const int* in_sizes, int n_in,
                              void* d_out, int out_size)
{
    const float4* roi   = (const float4*)d_in[0];
    const float4* gt    = (const float4*)d_in[1];
    const int*    gtlab = (const int*)d_in[2];

    dim3 gA((N_ROI + RPB - 1) / RPB, BATCH);
    iou_kernel<<<gA, 256>>>(roi, gt);
    select_kernel<<<BATCH, 1024>>>(roi, gt, gtlab);
    write_kernel<<<(ALL_VEC4 + 255) / 256, 256>>>((float4*)d_out);
}